// round 1
// baseline (speedup 1.0000x reference)
#include <cuda_runtime.h>
#include <math.h>

// Problem constants (fixed shapes from the dataset)
#define LEN   19947          // 100*150 + 50*75 + 25*38 + 13*19
#define DMODEL 256
#define NHEAD 8
#define DH    32
#define NLVL  4
#define NPTS  4

// Scratch buffers (device globals; no allocation allowed)
__device__ float g_value[LEN * DMODEL];   // value projection (LEN, M, DH)
__device__ float g_off  [LEN * 256];      // sampling offsets (LEN, M*L*P*2)
__device__ float g_attn [LEN * 128];      // attn logits -> softmax (LEN, M*L*P)
__device__ float g_mid  [LEN * DMODEL];   // sampled+weighted output (LEN, M*DH)

// ---------------------------------------------------------------------------
// Tiled SGEMM: C[M,N] = A[M,256] @ B[256,N] + bias[N], optional row mask zeroing.
// BM=BN=64, BK=16, 256 threads, 4x4 per thread.
// ---------------------------------------------------------------------------
__global__ __launch_bounds__(256)
void sgemm_bias_kernel(const float* __restrict__ A,
                       const float* __restrict__ B,
                       const float* __restrict__ bias,
                       const unsigned char* __restrict__ mask, // may be null
                       float* __restrict__ C,
                       int Mrows, int Ncols)
{
    __shared__ float As[16][65];  // [k][m], padded
    __shared__ float Bs[16][64];  // [k][n]

    const int tid = threadIdx.x;
    const int block_m = blockIdx.y * 64;
    const int block_n = blockIdx.x * 64;

    const int tx = tid & 15;          // 0..15 -> 4 cols each
    const int ty = tid >> 4;          // 0..15 -> 4 rows each

    // load mapping
    const int a_row  = tid >> 2;           // 0..63
    const int a_col4 = (tid & 3) * 4;      // 0,4,8,12
    const int b_row  = tid >> 4;           // 0..15
    const int b_col4 = (tid & 15) * 4;     // 0..60

    float acc[4][4];
#pragma unroll
    for (int i = 0; i < 4; i++)
#pragma unroll
        for (int j = 0; j < 4; j++) acc[i][j] = 0.f;

    const int ar = block_m + a_row;
    const bool a_ok = (ar < Mrows);

    for (int k0 = 0; k0 < 256; k0 += 16) {
        float4 av = make_float4(0.f, 0.f, 0.f, 0.f);
        if (a_ok) av = *reinterpret_cast<const float4*>(A + (size_t)ar * 256 + k0 + a_col4);
        As[a_col4 + 0][a_row] = av.x;
        As[a_col4 + 1][a_row] = av.y;
        As[a_col4 + 2][a_row] = av.z;
        As[a_col4 + 3][a_row] = av.w;

        float4 bv = *reinterpret_cast<const float4*>(B + (size_t)(k0 + b_row) * Ncols + block_n + b_col4);
        *reinterpret_cast<float4*>(&Bs[b_row][b_col4]) = bv;

        __syncthreads();

#pragma unroll
        for (int k = 0; k < 16; k++) {
            float a[4], b[4];
#pragma unroll
            for (int i = 0; i < 4; i++) a[i] = As[k][ty * 4 + i];
#pragma unroll
            for (int j = 0; j < 4; j++) b[j] = Bs[k][tx * 4 + j];
#pragma unroll
            for (int i = 0; i < 4; i++)
#pragma unroll
                for (int j = 0; j < 4; j++) acc[i][j] = fmaf(a[i], b[j], acc[i][j]);
        }
        __syncthreads();
    }

    float bv[4];
#pragma unroll
    for (int j = 0; j < 4; j++) bv[j] = bias[block_n + tx * 4 + j];

#pragma unroll
    for (int i = 0; i < 4; i++) {
        int r = block_m + ty * 4 + i;
        if (r >= Mrows) continue;
        float scale = 1.f;
        if (mask && mask[r]) scale = 0.f;
#pragma unroll
        for (int j = 0; j < 4; j++) {
            C[(size_t)r * Ncols + block_n + tx * 4 + j] = (acc[i][j] + bv[j]) * scale;
        }
    }
}

// ---------------------------------------------------------------------------
// Softmax over 16 values per (query, head), in place on g_attn.
// ---------------------------------------------------------------------------
__global__ void softmax16_kernel(float* __restrict__ attn, int total)
{
    int t = blockIdx.x * blockDim.x + threadIdx.x;  // t = q*8 + m
    if (t >= total) return;
    float* p = attn + (size_t)t * 16;
    float v[16];
    float mx = -1e30f;
#pragma unroll
    for (int i = 0; i < 16; i++) { v[i] = p[i]; mx = fmaxf(mx, v[i]); }
    float s = 0.f;
#pragma unroll
    for (int i = 0; i < 16; i++) { v[i] = __expf(v[i] - mx); s += v[i]; }
    float inv = 1.f / s;
#pragma unroll
    for (int i = 0; i < 16; i++) p[i] = v[i] * inv;
}

// ---------------------------------------------------------------------------
// Deformable sampling: one block per query, one warp per head, lane = channel.
// ---------------------------------------------------------------------------
__global__ __launch_bounds__(256)
void sample_kernel(const float* __restrict__ value,
                   const float* __restrict__ off,
                   const float* __restrict__ aw,
                   const float* __restrict__ refp,
                   float* __restrict__ out)
{
    const int q    = blockIdx.x;
    const int m    = threadIdx.x >> 5;
    const int lane = threadIdx.x & 31;

    const int HH[NLVL] = {100, 50, 25, 13};
    const int WW[NLVL] = {150, 75, 38, 19};
    const int ST[NLVL] = {0, 15000, 18750, 19700};

    const float* vbase = value + m * DH + lane;
    float acc = 0.f;

#pragma unroll
    for (int l = 0; l < NLVL; l++) {
        const float rx = __ldg(refp + ((size_t)q * NLVL + l) * 2 + 0);
        const float ry = __ldg(refp + ((size_t)q * NLVL + l) * 2 + 1);
        const int W = WW[l], H = HH[l], start = ST[l];
        const float Wf = (float)W, Hf = (float)H;

#pragma unroll
        for (int p = 0; p < NPTS; p++) {
            const int oc = ((m * NLVL + l) * NPTS + p) * 2;
            const float ox = __ldg(off + (size_t)q * 256 + oc + 0);
            const float oy = __ldg(off + (size_t)q * 256 + oc + 1);

            float gx = 2.f * (rx + ox / Wf) - 1.f;
            float gy = 2.f * (ry + oy / Hf) - 1.f;
            gx = fminf(fmaxf(gx, -2.f), 2.f);
            gy = fminf(fmaxf(gy, -2.f), 2.f);

            const float x = (gx + 1.f) * (Wf * 0.5f) - 0.5f;
            const float y = (gy + 1.f) * (Hf * 0.5f) - 0.5f;

            const float x0f = floorf(x), y0f = floorf(y);
            const float wx1 = x - x0f, wx0 = 1.f - wx1;
            const float wy1 = y - y0f, wy0 = 1.f - wy1;
            const int x0 = (int)x0f, y0 = (int)y0f;
            const int x1 = x0 + 1,  y1 = y0 + 1;

            const bool vx0 = (x0 >= 0) & (x0 < W);
            const bool vx1 = (x1 >= 0) & (x1 < W);
            const bool vy0 = (y0 >= 0) & (y0 < H);
            const bool vy1 = (y1 >= 0) & (y1 < H);

            float s = 0.f;
            if (vx0 & vy0) s += (wx0 * wy0) * __ldg(vbase + (size_t)(start + y0 * W + x0) * DMODEL);
            if (vx1 & vy0) s += (wx1 * wy0) * __ldg(vbase + (size_t)(start + y0 * W + x1) * DMODEL);
            if (vx0 & vy1) s += (wx0 * wy1) * __ldg(vbase + (size_t)(start + y1 * W + x0) * DMODEL);
            if (vx1 & vy1) s += (wx1 * wy1) * __ldg(vbase + (size_t)(start + y1 * W + x1) * DMODEL);

            const float a = __ldg(aw + (size_t)q * 128 + m * 16 + l * NPTS + p);
            acc = fmaf(a, s, acc);
        }
    }
    out[(size_t)q * DMODEL + m * DH + lane] = acc;
}

// ---------------------------------------------------------------------------
// Launch
// ---------------------------------------------------------------------------
extern "C" void kernel_launch(void* const* d_in, const int* in_sizes, int n_in,
                              void* d_out, int out_size)
{
    const float* query  = (const float*)d_in[0];
    const float* refp   = (const float*)d_in[1];
    const float* inflat = (const float*)d_in[2];
    const unsigned char* pmask = (const unsigned char*)d_in[3];
    const float* W_off  = (const float*)d_in[4];
    const float* b_off  = (const float*)d_in[5];
    const float* W_attn = (const float*)d_in[6];
    const float* b_attn = (const float*)d_in[7];
    const float* W_val  = (const float*)d_in[8];
    const float* b_val  = (const float*)d_in[9];
    const float* W_out  = (const float*)d_in[10];
    const float* b_out  = (const float*)d_in[11];
    float* out = (float*)d_out;

    float *pval, *poff, *pattn, *pmid;
    cudaGetSymbolAddress((void**)&pval,  g_value);
    cudaGetSymbolAddress((void**)&poff,  g_off);
    cudaGetSymbolAddress((void**)&pattn, g_attn);
    cudaGetSymbolAddress((void**)&pmid,  g_mid);

    const int Mr = LEN;
    dim3 grid256((256 + 63) / 64, (Mr + 63) / 64);
    dim3 grid128((128 + 63) / 64, (Mr + 63) / 64);

    // 1. value projection (with padding mask)
    sgemm_bias_kernel<<<grid256, 256>>>(inflat, W_val, b_val, pmask, pval, Mr, 256);
    // 2. sampling offsets
    sgemm_bias_kernel<<<grid256, 256>>>(query, W_off, b_off, nullptr, poff, Mr, 256);
    // 3. attention logits
    sgemm_bias_kernel<<<grid128, 256>>>(query, W_attn, b_attn, nullptr, pattn, Mr, 128);
    // 4. softmax over 16 per (q, head)
    {
        int total = Mr * NHEAD;
        softmax16_kernel<<<(total + 255) / 256, 256>>>(pattn, total);
    }
    // 5. deformable bilinear sampling + weighted sum
    sample_kernel<<<Mr, 256>>>(pval, poff, pattn, refp, pmid);
    // 6. output projection
    sgemm_bias_kernel<<<grid256, 256>>>(pmid, W_out, b_out, nullptr, out, Mr, 256);
}

// round 3
// speedup vs baseline: 1.0773x; 1.0773x over previous
#include <cuda_runtime.h>
#include <cuda_bf16.h>
#include <mma.h>
#include <cstdint>
#include <math.h>

using namespace nvcuda;

// Problem constants
#define LEN    19947
#define NHEAD  8
#define DH     32
#define NLVL   4
#define NPTS   4

// ---------------------------------------------------------------------------
// Scratch (device globals; no allocation allowed)
// ---------------------------------------------------------------------------
__device__ float g_value[LEN * 256];
__device__ float g_off  [LEN * 256];
__device__ float g_attn [LEN * 128];
__device__ float g_mid  [LEN * 256];

// Pre-split transposed weights: [N][K=256] bf16, hi/lo parts
__device__ __nv_bfloat16 g_wv_hi[256 * 256], g_wv_lo[256 * 256];
__device__ __nv_bfloat16 g_wo_hi[256 * 256], g_wo_lo[256 * 256];
__device__ __nv_bfloat16 g_wa_hi[128 * 256], g_wa_lo[128 * 256];
__device__ __nv_bfloat16 g_wu_hi[256 * 256], g_wu_lo[256 * 256];

// ---------------------------------------------------------------------------
// Weight prep: W [256 x N] fp32 -> Wt_hi/Wt_lo [N x 256] bf16
// ---------------------------------------------------------------------------
__global__ void prep_weight_kernel(const float* __restrict__ W, int Ncols,
                                   __nv_bfloat16* __restrict__ hi,
                                   __nv_bfloat16* __restrict__ lo) {
    int id = blockIdx.x * blockDim.x + threadIdx.x;
    if (id >= Ncols * 256) return;
    int n = id >> 8;
    int k = id & 255;
    float x = W[k * Ncols + n];
    __nv_bfloat16 h = __float2bfloat16_rn(x);
    hi[id] = h;
    lo[id] = __float2bfloat16_rn(x - __bfloat162float(h));
}

// ---------------------------------------------------------------------------
// WMMA bf16x3 GEMM: C[Mrows, Ncols] = A[Mrows, 256] @ B[256, Ncols] + bias
// Block tile 128x128, 8 warps (warp tile 32x64), K chunks of 32.
// bf16 error compensation: acc = Ah*Bh + Ah*Bl + Al*Bh  (fp32 accumulate).
// Optional: row mask zeroing, fused softmax over groups of 16.
// ---------------------------------------------------------------------------
#define ASTRIDE 40           // padded bf16 row stride for 32-wide K chunk
#define CSTRIDE 132          // padded fp32 stage stride
#define SMEM_BYTES (128 * CSTRIDE * 4)   // 67584 (stage is the max user)

__global__ __launch_bounds__(256, 1)
void gemm_wmma_kernel(const float* __restrict__ A,
                      const __nv_bfloat16* __restrict__ Bhi,
                      const __nv_bfloat16* __restrict__ Blo,
                      const float* __restrict__ bias,
                      const unsigned char* __restrict__ mask,
                      float* __restrict__ C,
                      int Mrows, int Ncols, int do_softmax)
{
    extern __shared__ char smem[];
    __nv_bfloat16* a_hi = reinterpret_cast<__nv_bfloat16*>(smem);
    __nv_bfloat16* a_lo = a_hi + 128 * ASTRIDE;
    __nv_bfloat16* b_hi = a_lo + 128 * ASTRIDE;
    __nv_bfloat16* b_lo = b_hi + 128 * ASTRIDE;
    float* stage = reinterpret_cast<float*>(smem);

    const int tid  = threadIdx.x;
    const int warp = tid >> 5;
    const int wm   = warp & 3;    // 4 m-tiles of 32 rows
    const int wn   = warp >> 2;   // 2 n-tiles of 64 cols
    const int block_m = blockIdx.y * 128;
    const int block_n = blockIdx.x * 128;

    wmma::fragment<wmma::accumulator, 16, 16, 16, float> acc[2][4];
#pragma unroll
    for (int i = 0; i < 2; i++)
#pragma unroll
        for (int j = 0; j < 4; j++) wmma::fill_fragment(acc[i][j], 0.f);

    const int lr = tid >> 1;             // 0..127 (row for loads)
    const int cb = (tid & 1) * 16;       // 0 or 16 (K offset)
    const int gr_a = block_m + lr;
    const bool a_ok = (gr_a < Mrows);

    for (int chunk = 0; chunk < 8; chunk++) {
        const int k0 = chunk * 32;

        // ---- A chunk: fp32 -> hi/lo bf16, padded smem ----
        {
            float4 v0 = make_float4(0.f,0.f,0.f,0.f), v1 = v0, v2 = v0, v3 = v0;
            if (a_ok) {
                const float* ap = A + (size_t)gr_a * 256 + k0 + cb;
                v0 = *reinterpret_cast<const float4*>(ap + 0);
                v1 = *reinterpret_cast<const float4*>(ap + 4);
                v2 = *reinterpret_cast<const float4*>(ap + 8);
                v3 = *reinterpret_cast<const float4*>(ap + 12);
            }
            float f[16] = {v0.x,v0.y,v0.z,v0.w, v1.x,v1.y,v1.z,v1.w,
                           v2.x,v2.y,v2.z,v2.w, v3.x,v3.y,v3.z,v3.w};
            __nv_bfloat16 h[16], l[16];
#pragma unroll
            for (int e = 0; e < 16; e++) {
                h[e] = __float2bfloat16_rn(f[e]);
                l[e] = __float2bfloat16_rn(f[e] - __bfloat162float(h[e]));
            }
            *reinterpret_cast<uint4*>(a_hi + lr * ASTRIDE + cb)     = *reinterpret_cast<uint4*>(h);
            *reinterpret_cast<uint4*>(a_hi + lr * ASTRIDE + cb + 8) = *reinterpret_cast<uint4*>(h + 8);
            *reinterpret_cast<uint4*>(a_lo + lr * ASTRIDE + cb)     = *reinterpret_cast<uint4*>(l);
            *reinterpret_cast<uint4*>(a_lo + lr * ASTRIDE + cb + 8) = *reinterpret_cast<uint4*>(l + 8);
        }
        // ---- B chunk: pre-split bf16 [N][256] -> padded smem ----
        {
            const size_t gb = (size_t)(block_n + lr) * 256 + k0 + cb;
            uint4 h0 = *reinterpret_cast<const uint4*>(Bhi + gb);
            uint4 h1 = *reinterpret_cast<const uint4*>(Bhi + gb + 8);
            uint4 l0 = *reinterpret_cast<const uint4*>(Blo + gb);
            uint4 l1 = *reinterpret_cast<const uint4*>(Blo + gb + 8);
            *reinterpret_cast<uint4*>(b_hi + lr * ASTRIDE + cb)     = h0;
            *reinterpret_cast<uint4*>(b_hi + lr * ASTRIDE + cb + 8) = h1;
            *reinterpret_cast<uint4*>(b_lo + lr * ASTRIDE + cb)     = l0;
            *reinterpret_cast<uint4*>(b_lo + lr * ASTRIDE + cb + 8) = l1;
        }
        __syncthreads();

        // ---- 3 compensation passes ----
        const __nv_bfloat16* ap[3] = {a_hi, a_hi, a_lo};
        const __nv_bfloat16* bp[3] = {b_hi, b_lo, b_hi};
#pragma unroll
        for (int pp = 0; pp < 3; pp++) {
#pragma unroll
            for (int ks = 0; ks < 32; ks += 16) {
                wmma::fragment<wmma::matrix_a, 16, 16, 16, __nv_bfloat16, wmma::row_major> fa[2];
                wmma::fragment<wmma::matrix_b, 16, 16, 16, __nv_bfloat16, wmma::col_major> fb[4];
#pragma unroll
                for (int i = 0; i < 2; i++)
                    wmma::load_matrix_sync(fa[i], ap[pp] + (wm * 32 + i * 16) * ASTRIDE + ks, ASTRIDE);
#pragma unroll
                for (int j = 0; j < 4; j++)
                    wmma::load_matrix_sync(fb[j], bp[pp] + (wn * 64 + j * 16) * ASTRIDE + ks, ASTRIDE);
#pragma unroll
                for (int i = 0; i < 2; i++)
#pragma unroll
                    for (int j = 0; j < 4; j++)
                        wmma::mma_sync(acc[i][j], fa[i], fb[j], acc[i][j]);
            }
        }
        __syncthreads();
    }

    // ---- stage accumulators to smem ----
#pragma unroll
    for (int i = 0; i < 2; i++)
#pragma unroll
        for (int j = 0; j < 4; j++)
            wmma::store_matrix_sync(stage + (wm * 32 + i * 16) * CSTRIDE + wn * 64 + j * 16,
                                    acc[i][j], CSTRIDE, wmma::mem_row_major);
    __syncthreads();

    // ---- epilogue: bias (+ softmax16) (+ mask), coalesced float4 stores ----
    {
        const int r  = tid >> 1;
        const int gr = block_m + r;
        if (gr < Mrows) {
            const int colb = (tid & 1) * 64;
            float scale = 1.f;
            if (mask != nullptr && mask[gr]) scale = 0.f;
#pragma unroll
            for (int g = 0; g < 64; g += 16) {
                float v[16];
#pragma unroll
                for (int c = 0; c < 16; c++)
                    v[c] = stage[r * CSTRIDE + colb + g + c] + __ldg(bias + block_n + colb + g + c);
                if (do_softmax) {
                    float mx = -1e30f;
#pragma unroll
                    for (int c = 0; c < 16; c++) mx = fmaxf(mx, v[c]);
                    float sum = 0.f;
#pragma unroll
                    for (int c = 0; c < 16; c++) { v[c] = __expf(v[c] - mx); sum += v[c]; }
                    float inv = 1.f / sum;
#pragma unroll
                    for (int c = 0; c < 16; c++) v[c] *= inv;
                }
                float* op = C + (size_t)gr * Ncols + block_n + colb + g;
#pragma unroll
                for (int c = 0; c < 16; c += 4) {
                    float4 o = make_float4(v[c] * scale, v[c+1] * scale,
                                           v[c+2] * scale, v[c+3] * scale);
                    *reinterpret_cast<float4*>(op + c) = o;
                }
            }
        }
    }
}

// ---------------------------------------------------------------------------
// Deformable sampling: one block per query, one warp per head, lane = channel.
// ---------------------------------------------------------------------------
__global__ __launch_bounds__(256)
void sample_kernel(const float* __restrict__ value,
                   const float* __restrict__ off,
                   const float* __restrict__ aw,
                   const float* __restrict__ refp,
                   float* __restrict__ out)
{
    const int q    = blockIdx.x;
    const int m    = threadIdx.x >> 5;
    const int lane = threadIdx.x & 31;

    const int HH[NLVL] = {100, 50, 25, 13};
    const int WW[NLVL] = {150, 75, 38, 19};
    const int ST[NLVL] = {0, 15000, 18750, 19700};

    const float* vbase = value + m * DH + lane;
    float acc = 0.f;

#pragma unroll
    for (int l = 0; l < NLVL; l++) {
        const float rx = __ldg(refp + ((size_t)q * NLVL + l) * 2 + 0);
        const float ry = __ldg(refp + ((size_t)q * NLVL + l) * 2 + 1);
        const int W = WW[l], H = HH[l], start = ST[l];
        const float Wf = (float)W, Hf = (float)H;

#pragma unroll
        for (int p = 0; p < NPTS; p++) {
            const int oc = ((m * NLVL + l) * NPTS + p) * 2;
            const float ox = __ldg(off + (size_t)q * 256 + oc + 0);
            const float oy = __ldg(off + (size_t)q * 256 + oc + 1);

            float gx = 2.f * (rx + ox / Wf) - 1.f;
            float gy = 2.f * (ry + oy / Hf) - 1.f;
            gx = fminf(fmaxf(gx, -2.f), 2.f);
            gy = fminf(fmaxf(gy, -2.f), 2.f);

            const float x = (gx + 1.f) * (Wf * 0.5f) - 0.5f;
            const float y = (gy + 1.f) * (Hf * 0.5f) - 0.5f;

            const float x0f = floorf(x), y0f = floorf(y);
            const float wx1 = x - x0f, wx0 = 1.f - wx1;
            const float wy1 = y - y0f, wy0 = 1.f - wy1;
            const int x0 = (int)x0f, y0 = (int)y0f;
            const int x1 = x0 + 1,  y1 = y0 + 1;

            const bool vx0 = (x0 >= 0) & (x0 < W);
            const bool vx1 = (x1 >= 0) & (x1 < W);
            const bool vy0 = (y0 >= 0) & (y0 < H);
            const bool vy1 = (y1 >= 0) & (y1 < H);

            float s = 0.f;
            if (vx0 & vy0) s += (wx0 * wy0) * __ldg(vbase + (size_t)(start + y0 * W + x0) * 256);
            if (vx1 & vy0) s += (wx1 * wy0) * __ldg(vbase + (size_t)(start + y0 * W + x1) * 256);
            if (vx0 & vy1) s += (wx0 * wy1) * __ldg(vbase + (size_t)(start + y1 * W + x0) * 256);
            if (vx1 & vy1) s += (wx1 * wy1) * __ldg(vbase + (size_t)(start + y1 * W + x1) * 256);

            const float a = __ldg(aw + (size_t)q * 128 + m * 16 + l * NPTS + p);
            acc = fmaf(a, s, acc);
        }
    }
    out[(size_t)q * 256 + m * DH + lane] = acc;
}

// ---------------------------------------------------------------------------
// Launch
// ---------------------------------------------------------------------------
extern "C" void kernel_launch(void* const* d_in, const int* in_sizes, int n_in,
                              void* d_out, int out_size)
{
    const float* query  = (const float*)d_in[0];
    const float* refp   = (const float*)d_in[1];
    const float* inflat = (const float*)d_in[2];
    const unsigned char* pmask = (const unsigned char*)d_in[3];
    const float* W_off  = (const float*)d_in[4];
    const float* b_off  = (const float*)d_in[5];
    const float* W_attn = (const float*)d_in[6];
    const float* b_attn = (const float*)d_in[7];
    const float* W_val  = (const float*)d_in[8];
    const float* b_val  = (const float*)d_in[9];
    const float* W_out  = (const float*)d_in[10];
    const float* b_out  = (const float*)d_in[11];
    float* out = (float*)d_out;

    float *pval, *poff, *pattn, *pmid;
    cudaGetSymbolAddress((void**)&pval,  g_value);
    cudaGetSymbolAddress((void**)&poff,  g_off);
    cudaGetSymbolAddress((void**)&pattn, g_attn);
    cudaGetSymbolAddress((void**)&pmid,  g_mid);

    __nv_bfloat16 *wv_hi, *wv_lo, *wo_hi, *wo_lo, *wa_hi, *wa_lo, *wu_hi, *wu_lo;
    cudaGetSymbolAddress((void**)&wv_hi, g_wv_hi);
    cudaGetSymbolAddress((void**)&wv_lo, g_wv_lo);
    cudaGetSymbolAddress((void**)&wo_hi, g_wo_hi);
    cudaGetSymbolAddress((void**)&wo_lo, g_wo_lo);
    cudaGetSymbolAddress((void**)&wa_hi, g_wa_hi);
    cudaGetSymbolAddress((void**)&wa_lo, g_wa_lo);
    cudaGetSymbolAddress((void**)&wu_hi, g_wu_hi);
    cudaGetSymbolAddress((void**)&wu_lo, g_wu_lo);

    cudaFuncSetAttribute(gemm_wmma_kernel,
                         cudaFuncAttributeMaxDynamicSharedMemorySize, SMEM_BYTES);

    const int Mr = LEN;

    // weight prep (tiny)
    prep_weight_kernel<<<(256 * 256 + 255) / 256, 256>>>(W_val,  256, wv_hi, wv_lo);
    prep_weight_kernel<<<(256 * 256 + 255) / 256, 256>>>(W_off,  256, wo_hi, wo_lo);
    prep_weight_kernel<<<(128 * 256 + 255) / 256, 256>>>(W_attn, 128, wa_hi, wa_lo);
    prep_weight_kernel<<<(256 * 256 + 255) / 256, 256>>>(W_out,  256, wu_hi, wu_lo);

    dim3 g256(2, (Mr + 127) / 128);
    dim3 g128(1, (Mr + 127) / 128);

    // 1. value projection (with padding mask)
    gemm_wmma_kernel<<<g256, 256, SMEM_BYTES>>>(inflat, wv_hi, wv_lo, b_val, pmask, pval, Mr, 256, 0);
    // 2. sampling offsets
    gemm_wmma_kernel<<<g256, 256, SMEM_BYTES>>>(query, wo_hi, wo_lo, b_off, nullptr, poff, Mr, 256, 0);
    // 3. attention logits + fused softmax over 16 per (q, head)
    gemm_wmma_kernel<<<g128, 256, SMEM_BYTES>>>(query, wa_hi, wa_lo, b_attn, nullptr, pattn, Mr, 128, 1);
    // 4. deformable bilinear sampling + weighted sum
    sample_kernel<<<Mr, 256>>>(pval, poff, pattn, refp, pmid);
    // 5. output projection
    gemm_wmma_kernel<<<g256, 256, SMEM_BYTES>>>(pmid, wu_hi, wu_lo, b_out, nullptr, out, Mr, 256, 0);
}

// round 4
// speedup vs baseline: 1.2484x; 1.1588x over previous
#include <cuda_runtime.h>
#include <cuda_bf16.h>
#include <cuda_fp16.h>
#include <mma.h>
#include <cstdint>
#include <math.h>

using namespace nvcuda;

#define LEN    19947
#define NHEAD  8
#define DH     32
#define NLVL   4
#define NPTS   4

// ---------------------------------------------------------------------------
// Scratch (device globals)
// ---------------------------------------------------------------------------
__device__ __half g_value_h[LEN * 256];              // fp16 value for sampler
__device__ float  g_off [LEN * 256];
__device__ float  g_attn[LEN * 128];
__device__ __nv_bfloat16 g_mid_hi[LEN * 256], g_mid_lo[LEN * 256];
__device__ __nv_bfloat16 g_q_hi [LEN * 256], g_q_lo [LEN * 256];   // query split
__device__ __nv_bfloat16 g_f_hi [LEN * 256], g_f_lo [LEN * 256];   // inflat split
// packed weights: [0,256) = W_val^T, [256,640) = [W_off|W_attn]^T, [640,896) = W_out^T
__device__ __nv_bfloat16 g_w_hi[896 * 256], g_w_lo[896 * 256];

__device__ __forceinline__ uint32_t smem_u32(const void* p) {
    uint32_t a;
    asm("{ .reg .u64 t; cvta.to.shared.u64 t, %1; cvt.u32.u64 %0, t; }" : "=r"(a) : "l"(p));
    return a;
}

// ---------------------------------------------------------------------------
// Prep: pack + transpose + hi/lo split the three weight matrices
// ---------------------------------------------------------------------------
__global__ void prep_weights_kernel(const float* __restrict__ W_val,
                                    const float* __restrict__ W_off,
                                    const float* __restrict__ W_attn,
                                    const float* __restrict__ W_out,
                                    __nv_bfloat16* __restrict__ hi,
                                    __nv_bfloat16* __restrict__ lo)
{
    int id = blockIdx.x * blockDim.x + threadIdx.x;
    if (id >= 896 * 256) return;
    int n = id >> 8;      // packed output row
    int k = id & 255;
    float x;
    if (n < 256)       x = W_val [k * 256 + n];
    else if (n < 512)  x = W_off [k * 256 + (n - 256)];
    else if (n < 640)  x = W_attn[k * 128 + (n - 512)];
    else               x = W_out [k * 256 + (n - 640)];
    __nv_bfloat16 h = __float2bfloat16_rn(x);
    hi[id] = h;
    lo[id] = __float2bfloat16_rn(x - __bfloat162float(h));
}

// ---------------------------------------------------------------------------
// Prep: split query and inflat (fp32 -> bf16 hi/lo), float4 granularity
// ---------------------------------------------------------------------------
__global__ void prep_split_kernel(const float* __restrict__ query,
                                  const float* __restrict__ inflat,
                                  __nv_bfloat16* __restrict__ qhi, __nv_bfloat16* __restrict__ qlo,
                                  __nv_bfloat16* __restrict__ fhi, __nv_bfloat16* __restrict__ flo)
{
    const int total4 = LEN * 256 / 4;
    int id = blockIdx.x * blockDim.x + threadIdx.x;
    if (id >= 2 * total4) return;
    const float* src;
    __nv_bfloat16 *dhi, *dlo;
    int i4 = id;
    if (id < total4) { src = query;  dhi = qhi; dlo = qlo; }
    else             { src = inflat; dhi = fhi; dlo = flo; i4 -= total4; }
    float4 v = *reinterpret_cast<const float4*>(src + (size_t)i4 * 4);
    float f[4] = {v.x, v.y, v.z, v.w};
    __nv_bfloat16 h[4], l[4];
#pragma unroll
    for (int e = 0; e < 4; e++) {
        h[e] = __float2bfloat16_rn(f[e]);
        l[e] = __float2bfloat16_rn(f[e] - __bfloat162float(h[e]));
    }
    *reinterpret_cast<uint2*>(dhi + (size_t)i4 * 4) = *reinterpret_cast<uint2*>(h);
    *reinterpret_cast<uint2*>(dlo + (size_t)i4 * 4) = *reinterpret_cast<uint2*>(l);
}

// ---------------------------------------------------------------------------
// GEMM: C = A @ B^T + bias, A pre-split bf16 hi/lo [Mrows x 256],
// B pre-split bf16 hi/lo [Ntot x 256]. bf16x3 compensation, fp32 accum.
// Block tile 128x128, 8 warps (32x64 each), BK=32, 2-stage cp.async pipeline.
// mode 0: float out C1 (+bias1)
// mode 1: half  out C1 (+bias1, mask zeroing)      [value projection]
// mode 2: dual: cols<256 -> float C1 (+bias1); cols>=256 -> softmax16 float C2 (+bias2)
// ---------------------------------------------------------------------------
#define ASTR 40
#define BUFB 10240                    // bytes per operand buffer (128*40*2)
#define STAGEB (4 * BUFB)             // 40960 per pipeline stage
#define CSTRIDE 132
#define GEMM_SMEM (2 * STAGEB)        // 81920 (epilogue stage fits: 128*132*4=67584)

#define CP16(dst, src, sz) \
    asm volatile("cp.async.cg.shared.global [%0], [%1], 16, %2;" \
                 :: "r"(dst), "l"(src), "r"(sz))
#define CP_COMMIT() asm volatile("cp.async.commit_group;")
#define CP_WAIT1()  asm volatile("cp.async.wait_group 1;")
#define CP_WAIT0()  asm volatile("cp.async.wait_group 0;")

__global__ __launch_bounds__(256, 1)
void gemm_bf16x3_kernel(const __nv_bfloat16* __restrict__ Ahi,
                        const __nv_bfloat16* __restrict__ Alo,
                        const __nv_bfloat16* __restrict__ Bhi,
                        const __nv_bfloat16* __restrict__ Blo,
                        const float* __restrict__ bias1,
                        const float* __restrict__ bias2,
                        const unsigned char* __restrict__ mask,
                        void* __restrict__ C1v, void* __restrict__ C2v,
                        int Mrows, int mode)
{
    extern __shared__ char smem[];
    const int tid  = threadIdx.x;
    const int warp = tid >> 5;
    const int wm   = warp & 3;
    const int wn   = warp >> 2;
    const int block_m = blockIdx.y * 128;
    const int block_n = blockIdx.x * 128;

    // cp.async mapping: 2 chunks of 16B per buffer per thread
    const int c0row = tid >> 1;                 // chunks tid*? -> use c = tid, tid+256
    const uint32_t sb = smem_u32(smem);

    wmma::fragment<wmma::accumulator, 16, 16, 16, float> acc[2][4];
#pragma unroll
    for (int i = 0; i < 2; i++)
#pragma unroll
        for (int j = 0; j < 4; j++) wmma::fill_fragment(acc[i][j], 0.f);

    // ---- async stage loader ----
    auto issue = [&](int chunk) {
        const int s = chunk & 1;
        const int k0 = chunk * 32;
        const uint32_t sbase = sb + s * STAGEB;
#pragma unroll
        for (int h = 0; h < 2; h++) {
            const int c   = tid + h * 256;      // 0..511
            const int row = c >> 2;
            const int prt = (c & 3) * 8;        // element offset in 32
            const uint32_t so = (uint32_t)(row * ASTR + prt) * 2;
            // A
            const int ga = block_m + row;
            const int asz = (ga < Mrows) ? 16 : 0;
            const size_t aoff = (size_t)ga * 256 + k0 + prt;
            CP16(sbase + 0 * BUFB + so, Ahi + aoff, asz);
            CP16(sbase + 1 * BUFB + so, Alo + aoff, asz);
            // B (N rows always valid: Ntot multiple of 128)
            const size_t boff = (size_t)(block_n + row) * 256 + k0 + prt;
            CP16(sbase + 2 * BUFB + so, Bhi + boff, 16);
            CP16(sbase + 3 * BUFB + so, Blo + boff, 16);
        }
    };

    issue(0);
    CP_COMMIT();

    for (int chunk = 0; chunk < 8; chunk++) {
        if (chunk < 7) { issue(chunk + 1); CP_COMMIT(); CP_WAIT1(); }
        else           { CP_WAIT0(); }
        __syncthreads();

        const int s = chunk & 1;
        const __nv_bfloat16* ahib = reinterpret_cast<const __nv_bfloat16*>(smem + s * STAGEB);
        const __nv_bfloat16* alob = ahib + 128 * ASTR;
        const __nv_bfloat16* bhib = alob + 128 * ASTR;
        const __nv_bfloat16* blob = bhib + 128 * ASTR;

#pragma unroll
        for (int ks = 0; ks < 32; ks += 16) {
            wmma::fragment<wmma::matrix_a, 16, 16, 16, __nv_bfloat16, wmma::row_major> fah[2], fal[2];
            wmma::fragment<wmma::matrix_b, 16, 16, 16, __nv_bfloat16, wmma::col_major> fbh[4], fbl[4];
#pragma unroll
            for (int i = 0; i < 2; i++)
                wmma::load_matrix_sync(fah[i], ahib + (wm * 32 + i * 16) * ASTR + ks, ASTR);
#pragma unroll
            for (int j = 0; j < 4; j++)
                wmma::load_matrix_sync(fbh[j], bhib + (wn * 64 + j * 16) * ASTR + ks, ASTR);
#pragma unroll
            for (int i = 0; i < 2; i++)
#pragma unroll
                for (int j = 0; j < 4; j++) wmma::mma_sync(acc[i][j], fah[i], fbh[j], acc[i][j]);
#pragma unroll
            for (int i = 0; i < 2; i++)
                wmma::load_matrix_sync(fal[i], alob + (wm * 32 + i * 16) * ASTR + ks, ASTR);
#pragma unroll
            for (int i = 0; i < 2; i++)
#pragma unroll
                for (int j = 0; j < 4; j++) wmma::mma_sync(acc[i][j], fal[i], fbh[j], acc[i][j]);
#pragma unroll
            for (int j = 0; j < 4; j++)
                wmma::load_matrix_sync(fbl[j], blob + (wn * 64 + j * 16) * ASTR + ks, ASTR);
#pragma unroll
            for (int i = 0; i < 2; i++)
#pragma unroll
                for (int j = 0; j < 4; j++) wmma::mma_sync(acc[i][j], fah[i], fbl[j], acc[i][j]);
        }
        __syncthreads();
    }

    // ---- stage accumulators to smem (reuses pipeline buffers) ----
    float* stage = reinterpret_cast<float*>(smem);
#pragma unroll
    for (int i = 0; i < 2; i++)
#pragma unroll
        for (int j = 0; j < 4; j++)
            wmma::store_matrix_sync(stage + (wm * 32 + i * 16) * CSTRIDE + wn * 64 + j * 16,
                                    acc[i][j], CSTRIDE, wmma::mem_row_major);
    __syncthreads();

    // ---- epilogue ----
    {
        const int r  = tid >> 1;
        const int gr = block_m + r;
        if (gr < Mrows) {
            const int colb = (tid & 1) * 64;
#pragma unroll
            for (int g = 0; g < 64; g += 16) {
                const int gcol = block_n + colb + g;
                float v[16];
                if (mode == 2 && gcol >= 256) {
#pragma unroll
                    for (int c = 0; c < 16; c++)
                        v[c] = stage[r * CSTRIDE + colb + g + c] + __ldg(bias2 + gcol - 256 + c);
                    float mx = -1e30f;
#pragma unroll
                    for (int c = 0; c < 16; c++) mx = fmaxf(mx, v[c]);
                    float sum = 0.f;
#pragma unroll
                    for (int c = 0; c < 16; c++) { v[c] = __expf(v[c] - mx); sum += v[c]; }
                    float inv = 1.f / sum;
                    float* C2 = reinterpret_cast<float*>(C2v);
#pragma unroll
                    for (int c = 0; c < 16; c += 4) {
                        float4 o = make_float4(v[c]*inv, v[c+1]*inv, v[c+2]*inv, v[c+3]*inv);
                        *reinterpret_cast<float4*>(C2 + (size_t)gr * 128 + gcol - 256 + c) = o;
                    }
                } else {
#pragma unroll
                    for (int c = 0; c < 16; c++)
                        v[c] = stage[r * CSTRIDE + colb + g + c] + __ldg(bias1 + gcol + c);
                    if (mode == 1) {
                        float scale = (mask != nullptr && mask[gr]) ? 0.f : 1.f;
                        __half* C1 = reinterpret_cast<__half*>(C1v);
                        __half hbuf[16];
#pragma unroll
                        for (int c = 0; c < 16; c++) hbuf[c] = __float2half_rn(v[c] * scale);
#pragma unroll
                        for (int c = 0; c < 16; c += 8)
                            *reinterpret_cast<uint4*>(C1 + (size_t)gr * 256 + gcol + c) =
                                *reinterpret_cast<uint4*>(hbuf + c);
                    } else {
                        float* C1 = reinterpret_cast<float*>(C1v);
#pragma unroll
                        for (int c = 0; c < 16; c += 4) {
                            float4 o = make_float4(v[c], v[c+1], v[c+2], v[c+3]);
                            *reinterpret_cast<float4*>(C1 + (size_t)gr * 256 + gcol + c) = o;
                        }
                    }
                }
            }
        }
    }
}

// ---------------------------------------------------------------------------
// Sampler: one block per query, one warp per head, lane = channel.
// Reads fp16 value, writes mid as bf16 hi/lo (feeds the out-projection GEMM).
// ---------------------------------------------------------------------------
__global__ __launch_bounds__(256)
void sample_kernel(const __half* __restrict__ value,
                   const float* __restrict__ off,
                   const float* __restrict__ aw,
                   const float* __restrict__ refp,
                   __nv_bfloat16* __restrict__ midhi,
                   __nv_bfloat16* __restrict__ midlo)
{
    const int q    = blockIdx.x;
    const int m    = threadIdx.x >> 5;
    const int lane = threadIdx.x & 31;

    const int HH[NLVL] = {100, 50, 25, 13};
    const int WW[NLVL] = {150, 75, 38, 19};
    const int ST[NLVL] = {0, 15000, 18750, 19700};

    const __half* vbase = value + m * DH + lane;
    float acc = 0.f;

#pragma unroll
    for (int l = 0; l < NLVL; l++) {
        const float rx = __ldg(refp + ((size_t)q * NLVL + l) * 2 + 0);
        const float ry = __ldg(refp + ((size_t)q * NLVL + l) * 2 + 1);
        const int W = WW[l], H = HH[l], start = ST[l];
        const float Wf = (float)W, Hf = (float)H;

#pragma unroll
        for (int p = 0; p < NPTS; p++) {
            const int oc = ((m * NLVL + l) * NPTS + p) * 2;
            const float ox = __ldg(off + (size_t)q * 256 + oc + 0);
            const float oy = __ldg(off + (size_t)q * 256 + oc + 1);

            float gx = 2.f * (rx + ox / Wf) - 1.f;
            float gy = 2.f * (ry + oy / Hf) - 1.f;
            gx = fminf(fmaxf(gx, -2.f), 2.f);
            gy = fminf(fmaxf(gy, -2.f), 2.f);

            const float x = (gx + 1.f) * (Wf * 0.5f) - 0.5f;
            const float y = (gy + 1.f) * (Hf * 0.5f) - 0.5f;

            const float x0f = floorf(x), y0f = floorf(y);
            const float wx1 = x - x0f, wx0 = 1.f - wx1;
            const float wy1 = y - y0f, wy0 = 1.f - wy1;
            const int x0 = (int)x0f, y0 = (int)y0f;
            const int x1 = x0 + 1,  y1 = y0 + 1;

            const bool vx0 = (x0 >= 0) & (x0 < W);
            const bool vx1 = (x1 >= 0) & (x1 < W);
            const bool vy0 = (y0 >= 0) & (y0 < H);
            const bool vy1 = (y1 >= 0) & (y1 < H);

            float s = 0.f;
            if (vx0 & vy0) s += (wx0 * wy0) * __half2float(__ldg(vbase + (size_t)(start + y0 * W + x0) * 256));
            if (vx1 & vy0) s += (wx1 * wy0) * __half2float(__ldg(vbase + (size_t)(start + y0 * W + x1) * 256));
            if (vx0 & vy1) s += (wx0 * wy1) * __half2float(__ldg(vbase + (size_t)(start + y1 * W + x0) * 256));
            if (vx1 & vy1) s += (wx1 * wy1) * __half2float(__ldg(vbase + (size_t)(start + y1 * W + x1) * 256));

            const float a = __ldg(aw + (size_t)q * 128 + m * 16 + l * NPTS + p);
            acc = fmaf(a, s, acc);
        }
    }
    const size_t oi = (size_t)q * 256 + m * DH + lane;
    __nv_bfloat16 h = __float2bfloat16_rn(acc);
    midhi[oi] = h;
    midlo[oi] = __float2bfloat16_rn(acc - __bfloat162float(h));
}

// ---------------------------------------------------------------------------
// Launch
// ---------------------------------------------------------------------------
extern "C" void kernel_launch(void* const* d_in, const int* in_sizes, int n_in,
                              void* d_out, int out_size)
{
    const float* query  = (const float*)d_in[0];
    const float* refp   = (const float*)d_in[1];
    const float* inflat = (const float*)d_in[2];
    const unsigned char* pmask = (const unsigned char*)d_in[3];
    const float* W_off  = (const float*)d_in[4];
    const float* b_off  = (const float*)d_in[5];
    const float* W_attn = (const float*)d_in[6];
    const float* b_attn = (const float*)d_in[7];
    const float* W_val  = (const float*)d_in[8];
    const float* b_val  = (const float*)d_in[9];
    const float* W_out  = (const float*)d_in[10];
    const float* b_out  = (const float*)d_in[11];
    float* out = (float*)d_out;

    __half* pval;   cudaGetSymbolAddress((void**)&pval,  g_value_h);
    float*  poff;   cudaGetSymbolAddress((void**)&poff,  g_off);
    float*  pattn;  cudaGetSymbolAddress((void**)&pattn, g_attn);
    __nv_bfloat16 *mid_hi, *mid_lo, *q_hi, *q_lo, *f_hi, *f_lo, *w_hi, *w_lo;
    cudaGetSymbolAddress((void**)&mid_hi, g_mid_hi);
    cudaGetSymbolAddress((void**)&mid_lo, g_mid_lo);
    cudaGetSymbolAddress((void**)&q_hi, g_q_hi);
    cudaGetSymbolAddress((void**)&q_lo, g_q_lo);
    cudaGetSymbolAddress((void**)&f_hi, g_f_hi);
    cudaGetSymbolAddress((void**)&f_lo, g_f_lo);
    cudaGetSymbolAddress((void**)&w_hi, g_w_hi);
    cudaGetSymbolAddress((void**)&w_lo, g_w_lo);

    cudaFuncSetAttribute(gemm_bf16x3_kernel,
                         cudaFuncAttributeMaxDynamicSharedMemorySize, GEMM_SMEM);

    const int Mr = LEN;
    const int mtiles = (Mr + 127) / 128;

    // prep
    prep_weights_kernel<<<(896 * 256 + 255) / 256, 256>>>(W_val, W_off, W_attn, W_out, w_hi, w_lo);
    prep_split_kernel<<<(2 * LEN * 64 + 255) / 256, 256>>>(query, inflat, q_hi, q_lo, f_hi, f_lo);

    const __nv_bfloat16* wv_hi = w_hi;              const __nv_bfloat16* wv_lo = w_lo;
    const __nv_bfloat16* woa_hi = w_hi + 256 * 256; const __nv_bfloat16* woa_lo = w_lo + 256 * 256;
    const __nv_bfloat16* wu_hi = w_hi + 640 * 256;  const __nv_bfloat16* wu_lo = w_lo + 640 * 256;

    // 1. value projection -> fp16 (mode 1, mask)
    gemm_bf16x3_kernel<<<dim3(2, mtiles), 256, GEMM_SMEM>>>(
        f_hi, f_lo, wv_hi, wv_lo, b_val, nullptr, pmask, pval, nullptr, Mr, 1);
    // 2. offsets + attn logits + softmax (mode 2, N=384)
    gemm_bf16x3_kernel<<<dim3(3, mtiles), 256, GEMM_SMEM>>>(
        q_hi, q_lo, woa_hi, woa_lo, b_off, b_attn, nullptr, poff, pattn, Mr, 2);
    // 3. sampler (emits mid hi/lo bf16)
    sample_kernel<<<Mr, 256>>>(pval, poff, pattn, refp, mid_hi, mid_lo);
    // 4. output projection (mode 0)
    gemm_bf16x3_kernel<<<dim3(2, mtiles), 256, GEMM_SMEM>>>(
        mid_hi, mid_lo, wu_hi, wu_lo, b_out, nullptr, nullptr, out, nullptr, Mr, 0);
}